// round 1
// baseline (speedup 1.0000x reference)
#include <cuda_runtime.h>
#include <math.h>

#define NB 8
#define HWN 1024
#define CD 128
#define NF 900
#define FSZ 9
#define EPSV 1e-5f
#define TPAD 132

// Scratch (device globals: allocation is forbidden)
__device__ float  g_Q[NB * HWN * CD];
__device__ float  g_K[NB * HWN * CD];
__device__ float  g_V[NB * HWN];
__device__ float  g_expS[(size_t)NB * HWN * HWN];   // 32 MB
__device__ double g_E[NB * HWN];
__device__ double g_G[NB * HWN];

extern __shared__ float smem_dyn[];

__global__ void zero_eg() {
    int i = blockIdx.x * blockDim.x + threadIdx.x;
    if (i < NB * HWN) { g_E[i] = 0.0; g_G[i] = 0.0; }
}

// Load a 128x128 f32 tile from global (row-major, k contiguous) into smem
// transposed: dst[k * TPAD + row]. Coalesced float4 global reads.
__device__ __forceinline__ void load_tile_T(float* dst, const float* __restrict__ src, int tid) {
#pragma unroll
    for (int i = 0; i < 16; i++) {
        int f4 = tid + i * 256;          // 0..4095
        int r  = f4 >> 5;                // row 0..127
        int k4 = (f4 & 31) << 2;         // k 0..124
        float4 v = reinterpret_cast<const float4*>(src + (size_t)r * CD)[f4 & 31];
        dst[(k4 + 0) * TPAD + r] = v.x;
        dst[(k4 + 1) * TPAD + r] = v.y;
        dst[(k4 + 2) * TPAD + r] = v.z;
        dst[(k4 + 3) * TPAD + r] = v.w;
    }
}

// 8x8 micro-tile over K=128; As/Bs transposed [k][row].
__device__ __forceinline__ void mma128(const float* As, const float* Bs,
                                       int r0, int c0, float acc[8][8]) {
#pragma unroll 2
    for (int k = 0; k < CD; k++) {
        float4 a0 = *reinterpret_cast<const float4*>(&As[k * TPAD + r0]);
        float4 a1 = *reinterpret_cast<const float4*>(&As[k * TPAD + r0 + 4]);
        float4 b0 = *reinterpret_cast<const float4*>(&Bs[k * TPAD + c0]);
        float4 b1 = *reinterpret_cast<const float4*>(&Bs[k * TPAD + c0 + 4]);
        float a[8] = {a0.x, a0.y, a0.z, a0.w, a1.x, a1.y, a1.z, a1.w};
        float b[8] = {b0.x, b0.y, b0.z, b0.w, b1.x, b1.y, b1.z, b1.w};
#pragma unroll
        for (int r = 0; r < 8; r++)
#pragma unroll
            for (int c = 0; c < 8; c++)
                acc[r][c] += a[r] * b[c];
    }
}

// Q = x @ Wq^T + bq ; K = x @ Wk^T + bk   (blockIdx.y selects Q/K)
__global__ void gemm_qk(const float* __restrict__ x,
                        const float* __restrict__ Wq, const float* __restrict__ bq,
                        const float* __restrict__ Wk, const float* __restrict__ bk) {
    float* As = smem_dyn;
    float* Bs = smem_dyn + CD * TPAD;
    int tid = threadIdx.x;
    const float* W    = blockIdx.y ? Wk : Wq;
    const float* bias = blockIdx.y ? bk : bq;
    float* Out        = blockIdx.y ? g_K : g_Q;
    int row0 = blockIdx.x * 128;

    load_tile_T(As, x + (size_t)row0 * CD, tid);
    load_tile_T(Bs, W, tid);
    __syncthreads();

    int tx = tid & 15, ty = tid >> 4;
    int r0 = ty * 8, c0 = tx * 8;
    float acc[8][8] = {};
    mma128(As, Bs, r0, c0, acc);

#pragma unroll
    for (int r = 0; r < 8; r++) {
        float* orow = Out + (size_t)(row0 + r0 + r) * CD + c0;
#pragma unroll
        for (int c = 0; c < 8; c++) orow[c] = acc[r][c] + bias[c0 + c];
    }
}

// V[row] = x[row,:] . wv + bv   (one warp per row)
__global__ void v_kernel(const float* __restrict__ x, const float* __restrict__ wv,
                         const float* __restrict__ bv) {
    int row  = blockIdx.x * 8 + (threadIdx.x >> 5);
    int lane = threadIdx.x & 31;
    const float* xr = x + (size_t)row * CD;
    float s = 0.f;
#pragma unroll
    for (int k = lane; k < CD; k += 32) s += xr[k] * wv[k];
#pragma unroll
    for (int off = 16; off; off >>= 1) s += __shfl_xor_sync(0xffffffffu, s, off);
    if (lane == 0) g_V[row] = s + bv[0];
}

// expS = exp(Q @ K^T) per batch; fused row sums E (exp) and G (exp*V).
__global__ void gemm_s() {
    __shared__ float Vs[128];
    float* As = smem_dyn;
    float* Bs = smem_dyn + CD * TPAD;
    int tid = threadIdx.x;
    int b  = blockIdx.z;
    int p0 = blockIdx.y * 128, q0 = blockIdx.x * 128;

    load_tile_T(As, g_Q + ((size_t)b * HWN + p0) * CD, tid);
    load_tile_T(Bs, g_K + ((size_t)b * HWN + q0) * CD, tid);
    if (tid < 128) Vs[tid] = g_V[b * HWN + q0 + tid];
    __syncthreads();

    int tx = tid & 15, ty = tid >> 4;
    int r0 = ty * 8, c0 = tx * 8;
    float acc[8][8] = {};
    mma128(As, Bs, r0, c0, acc);

#pragma unroll
    for (int r = 0; r < 8; r++) {
        int p = p0 + r0 + r;
        float e[8];
        float esum = 0.f, gsum = 0.f;
#pragma unroll
        for (int c = 0; c < 8; c++) {
            e[c]  = __expf(acc[r][c]);
            esum += e[c];
            gsum += e[c] * Vs[c0 + c];
        }
        float* dst = g_expS + ((size_t)b * HWN + p) * HWN + q0 + c0;
        reinterpret_cast<float4*>(dst)[0] = make_float4(e[0], e[1], e[2], e[3]);
        reinterpret_cast<float4*>(dst)[1] = make_float4(e[4], e[5], e[6], e[7]);

        double de = (double)esum, dg = (double)gsum;
#pragma unroll
        for (int off = 8; off >= 1; off >>= 1) {   // reduce across 16 tx lanes
            de += __shfl_xor_sync(0xffffffffu, de, off);
            dg += __shfl_xor_sync(0xffffffffu, dg, off);
        }
        if (tx == 0) {
            atomicAdd(&g_E[b * HWN + p], de);
            atomicAdd(&g_G[b * HWN + p], dg);
        }
    }
}

// Per (b,f): 9 gates via masked-correction, then out[b,f,c] = sum_p gate[p]*x[idx[p]][c]
__global__ void out_kernel(const float* __restrict__ x, const int* __restrict__ lidx,
                           float* __restrict__ out) {
    int bf = blockIdx.x;
    int b = bf / NF, f = bf - b * NF;
    __shared__ int   sidx[FSZ];
    __shared__ float sgate[FSZ];
    int t = threadIdx.x;
    if (t < FSZ) sidx[t] = lidx[f * FSZ + t];
    __syncthreads();
    if (t < FSZ) {
        int p = sidx[t];
        const float* erow = g_expS + ((size_t)b * HWN + p) * HWN;
        double num = g_G[b * HWN + p];
        double den = g_E[b * HWN + p];
#pragma unroll
        for (int j = 0; j < FSZ; j++) {
            int q = sidx[j];
            double e = (double)erow[q];
            num -= e * (double)g_V[b * HWN + q];
            den -= e;
        }
        sgate[t] = (float)(num / (den + (double)EPSV));
    }
    __syncthreads();
    const float* xb = x + (size_t)b * HWN * CD;
    float o = 0.f;
#pragma unroll
    for (int p = 0; p < FSZ; p++)
        o += sgate[p] * xb[(size_t)sidx[p] * CD + t];
    out[(size_t)bf * CD + t] = o;
}

extern "C" void kernel_launch(void* const* d_in, const int* in_sizes, int n_in,
                              void* d_out, int out_size) {
    const float* batch = (const float*)d_in[0];
    const float* Wq    = (const float*)d_in[1];
    const float* bq    = (const float*)d_in[2];
    const float* Wk    = (const float*)d_in[3];
    const float* bk    = (const float*)d_in[4];
    const float* wv    = (const float*)d_in[5];
    const float* bv    = (const float*)d_in[6];
    // d_in[7] = gmask (unused: mask handled analytically via local_indices)
    const int*   lidx  = (const int*)d_in[8];
    float* out = (float*)d_out;

    size_t smem = (size_t)2 * CD * TPAD * sizeof(float);   // 135168 B
    cudaFuncSetAttribute(gemm_qk, cudaFuncAttributeMaxDynamicSharedMemorySize, (int)smem);
    cudaFuncSetAttribute(gemm_s,  cudaFuncAttributeMaxDynamicSharedMemorySize, (int)smem);

    zero_eg<<<(NB * HWN + 255) / 256, 256>>>();
    gemm_qk<<<dim3(64, 2), 256, smem>>>(batch, Wq, bq, Wk, bk);
    v_kernel<<<NB * HWN / 8, 256>>>(batch, wv, bv);
    gemm_s<<<dim3(8, 8, NB), 256, smem>>>();
    out_kernel<<<NB * NF, 128>>>(batch, lidx, out);
}

// round 4
// speedup vs baseline: 2.1846x; 2.1846x over previous
#include <cuda_runtime.h>
#include <cuda_bf16.h>
#include <cstdint>
#include <math.h>

#define NB 8
#define HWN 1024
#define CD 128
#define NF 900
#define FSZ 9
#define EPSV 1e-5f
#define ROWB 272          // padded row stride in bytes (136 bf16) -> conflict-free ldmatrix
#define TILEB (128 * ROWB)

// ---------------- scratch (device globals; allocation forbidden) ------------
__device__ __nv_bfloat16 g_xh[NB * HWN * CD];
__device__ __nv_bfloat16 g_xl[NB * HWN * CD];
__device__ __nv_bfloat16 g_Wqh[CD * CD];
__device__ __nv_bfloat16 g_Wql[CD * CD];
__device__ __nv_bfloat16 g_Wkh[CD * CD];
__device__ __nv_bfloat16 g_Wkl[CD * CD];
__device__ __nv_bfloat16 g_Qh[NB * HWN * CD];
__device__ __nv_bfloat16 g_Ql[NB * HWN * CD];
__device__ __nv_bfloat16 g_Kh[NB * HWN * CD];
__device__ __nv_bfloat16 g_Kl[NB * HWN * CD];
__device__ float  g_V[NB * HWN];
__device__ float  g_expS[(size_t)NB * HWN * HWN];   // 32 MB
__device__ double g_E[NB * HWN];
__device__ double g_G[NB * HWN];

// smem layout: [0..512) aux (bias or V), tiles at 1024
#define SM_AUX  0
#define SM_AH   1024
#define SM_AL   (SM_AH + TILEB)
#define SM_BH   (SM_AL + TILEB)
#define SM_BL   (SM_BH + TILEB)
#define SM_TOTAL (SM_BL + TILEB)

extern __shared__ char smx[];

// ---------------- mma.sync helpers ------------------------------------------
__device__ __forceinline__ uint32_t smem_u32(const void* p) {
    uint32_t a;
    asm("{ .reg .u64 t; cvta.to.shared.u64 t, %1; cvt.u32.u64 %0, t; }" : "=r"(a) : "l"(p));
    return a;
}
__device__ __forceinline__ void ldsm4(uint32_t* r, uint32_t addr) {
    asm volatile("ldmatrix.sync.aligned.m8n8.x4.shared.b16 {%0,%1,%2,%3}, [%4];"
                 : "=r"(r[0]), "=r"(r[1]), "=r"(r[2]), "=r"(r[3]) : "r"(addr));
}
__device__ __forceinline__ void ldsm2(uint32_t* r, uint32_t addr) {
    asm volatile("ldmatrix.sync.aligned.m8n8.x2.shared.b16 {%0,%1}, [%2];"
                 : "=r"(r[0]), "=r"(r[1]) : "r"(addr));
}
__device__ __forceinline__ void mma_bf16(float* d, const uint32_t* a, const uint32_t* b) {
    asm volatile("mma.sync.aligned.m16n8k16.row.col.f32.bf16.bf16.f32 "
                 "{%0,%1,%2,%3}, {%4,%5,%6,%7}, {%8,%9}, {%0,%1,%2,%3};"
                 : "+f"(d[0]), "+f"(d[1]), "+f"(d[2]), "+f"(d[3])
                 : "r"(a[0]), "r"(a[1]), "r"(a[2]), "r"(a[3]), "r"(b[0]), "r"(b[1]));
}

// copy a [128][128] bf16 tile (row-major, 256B rows) into padded smem (272B rows)
__device__ __forceinline__ void copy_tile(char* sm, const __nv_bfloat16* __restrict__ src, int tid) {
#pragma unroll
    for (int j = 0; j < 8; j++) {
        int idx = tid + j * 256;          // 0..2047 chunks of 16B
        int row = idx >> 4;
        int c   = idx & 15;
        uint4 v = reinterpret_cast<const uint4*>(src + (size_t)row * CD)[c];
        *reinterpret_cast<uint4*>(sm + row * ROWB + c * 16) = v;
    }
}

// one k-pass of a 128x128x128 bf16 GEMM term; warp tile 64x32 (wm 0..1, wn 0..3)
__device__ __forceinline__ void mma_term(uint32_t Abase, uint32_t Bbase,
                                         int wm, int wn, int lane, float acc[4][4][4]) {
    uint32_t aoff = Abase + (wm * 64 + (lane & 15)) * ROWB + (lane >> 4) * 16;
    uint32_t boff = Bbase + (wn * 32 + (lane & 7)) * ROWB + ((lane >> 3) & 1) * 16;
#pragma unroll
    for (int kk = 0; kk < 8; kk++) {
        uint32_t kb = kk * 32;            // 16 bf16 = 32 bytes
        uint32_t a[4][4], b[4][2];
#pragma unroll
        for (int mt = 0; mt < 4; mt++) ldsm4(a[mt], aoff + mt * 16 * ROWB + kb);
#pragma unroll
        for (int nt = 0; nt < 4; nt++) ldsm2(b[nt], boff + nt * 8 * ROWB + kb);
#pragma unroll
        for (int mt = 0; mt < 4; mt++)
#pragma unroll
            for (int nt = 0; nt < 4; nt++)
                mma_bf16(acc[mt][nt], a[mt], b[nt]);
    }
}

__device__ __forceinline__ void mma_triple(uint32_t sb, int wm, int wn, int lane,
                                           float acc[4][4][4]) {
    mma_term(sb + SM_AH, sb + SM_BH, wm, wn, lane, acc);   // Ah*Bh
    mma_term(sb + SM_AH, sb + SM_BL, wm, wn, lane, acc);   // Ah*Bl
    mma_term(sb + SM_AL, sb + SM_BH, wm, wn, lane, acc);   // Al*Bh
}

// ---------------- small kernels ---------------------------------------------
__global__ void zero_eg() {
    int i = blockIdx.x * blockDim.x + threadIdx.x;
    if (i < NB * HWN) { g_E[i] = 0.0; g_G[i] = 0.0; }
}

__global__ void split_kernel(const float* __restrict__ src, __nv_bfloat16* __restrict__ h,
                             __nv_bfloat16* __restrict__ l, int n) {
    int i = blockIdx.x * blockDim.x + threadIdx.x;
    if (i < n) {
        float v = src[i];
        __nv_bfloat16 hh = __float2bfloat16(v);
        float r = v - __bfloat162float(hh);
        h[i] = hh;
        l[i] = __float2bfloat16(r);
    }
}

__global__ void v_kernel(const float* __restrict__ x, const float* __restrict__ wv,
                         const float* __restrict__ bv) {
    int row  = blockIdx.x * 8 + (threadIdx.x >> 5);
    int lane = threadIdx.x & 31;
    const float* xr = x + (size_t)row * CD;
    float s = 0.f;
#pragma unroll
    for (int k = lane; k < CD; k += 32) s += xr[k] * wv[k];
#pragma unroll
    for (int off = 16; off; off >>= 1) s += __shfl_xor_sync(0xffffffffu, s, off);
    if (lane == 0) g_V[row] = s + bv[0];
}

// ---------------- projection GEMM (mma.sync) --------------------------------
// blockIdx.x: row tile (64), blockIdx.y: 0 = Q, 1 = K
__global__ __launch_bounds__(256, 1) void gemm_proj_tc(const float* __restrict__ bq,
                                                       const float* __restrict__ bk) {
    uint32_t sb = smem_u32(smx);
    int tid = threadIdx.x;
    int wid = tid >> 5, lane = tid & 31;
    int wm = wid & 1, wn = wid >> 1;
    int row0 = blockIdx.x * 128;
    bool isK = blockIdx.y != 0;

    const __nv_bfloat16* Wh = isK ? g_Wkh : g_Wqh;
    const __nv_bfloat16* Wl = isK ? g_Wkl : g_Wql;
    const float* bias = isK ? bk : bq;
    __nv_bfloat16* Oh = isK ? g_Kh : g_Qh;
    __nv_bfloat16* Ol = isK ? g_Kl : g_Ql;

    copy_tile(smx + SM_AH, g_xh + (size_t)row0 * CD, tid);
    copy_tile(smx + SM_AL, g_xl + (size_t)row0 * CD, tid);
    copy_tile(smx + SM_BH, Wh, tid);
    copy_tile(smx + SM_BL, Wl, tid);
    if (tid < 128) *reinterpret_cast<float*>(smx + SM_AUX + tid * 4) = bias[tid];
    __syncthreads();

    float acc[4][4][4];
#pragma unroll
    for (int mt = 0; mt < 4; mt++)
#pragma unroll
        for (int nt = 0; nt < 4; nt++)
#pragma unroll
            for (int i = 0; i < 4; i++) acc[mt][nt][i] = 0.f;

    mma_triple(sb, wm, wn, lane, acc);

    const float* bs = reinterpret_cast<const float*>(smx + SM_AUX);
#pragma unroll
    for (int mt = 0; mt < 4; mt++) {
        int rlo = row0 + wm * 64 + mt * 16 + (lane >> 2);
#pragma unroll
        for (int nt = 0; nt < 4; nt++) {
            int col = wn * 32 + nt * 8 + (lane & 3) * 2;
            float b0 = bs[col], b1 = bs[col + 1];
#pragma unroll
            for (int half = 0; half < 2; half++) {
                int row = rlo + half * 8;
                float v0 = acc[mt][nt][half * 2 + 0] + b0;
                float v1 = acc[mt][nt][half * 2 + 1] + b1;
                __nv_bfloat16 h0 = __float2bfloat16(v0);
                __nv_bfloat16 h1 = __float2bfloat16(v1);
                __nv_bfloat162 ph; ph.x = h0; ph.y = h1;
                __nv_bfloat162 pl;
                pl.x = __float2bfloat16(v0 - __bfloat162float(h0));
                pl.y = __float2bfloat16(v1 - __bfloat162float(h1));
                *reinterpret_cast<uint32_t*>(Oh + (size_t)row * CD + col) =
                    *reinterpret_cast<uint32_t*>(&ph);
                *reinterpret_cast<uint32_t*>(Ol + (size_t)row * CD + col) =
                    *reinterpret_cast<uint32_t*>(&pl);
            }
        }
    }
}

// ---------------- S = exp(Q K^T) + fused row sums ---------------------------
// grid (8 qtile, 8 ptile, 8 batch)
__global__ __launch_bounds__(256, 1) void gemm_s_tc() {
    uint32_t sb = smem_u32(smx);
    int tid = threadIdx.x;
    int wid = tid >> 5, lane = tid & 31;
    int wm = wid & 1, wn = wid >> 1;
    int b  = blockIdx.z;
    int q0 = blockIdx.x * 128, p0 = blockIdx.y * 128;

    size_t abase = ((size_t)b * HWN + p0) * CD;
    size_t bbase = ((size_t)b * HWN + q0) * CD;
    copy_tile(smx + SM_AH, g_Qh + abase, tid);
    copy_tile(smx + SM_AL, g_Ql + abase, tid);
    copy_tile(smx + SM_BH, g_Kh + bbase, tid);
    copy_tile(smx + SM_BL, g_Kl + bbase, tid);
    if (tid < 128) *reinterpret_cast<float*>(smx + SM_AUX + tid * 4) = g_V[b * HWN + q0 + tid];
    __syncthreads();

    float acc[4][4][4];
#pragma unroll
    for (int mt = 0; mt < 4; mt++)
#pragma unroll
        for (int nt = 0; nt < 4; nt++)
#pragma unroll
            for (int i = 0; i < 4; i++) acc[mt][nt][i] = 0.f;

    mma_triple(sb, wm, wn, lane, acc);

    const float* Vs = reinterpret_cast<const float*>(smx + SM_AUX);
    float esum[4][2], gsum[4][2];
#pragma unroll
    for (int mt = 0; mt < 4; mt++) {
        esum[mt][0] = esum[mt][1] = 0.f;
        gsum[mt][0] = gsum[mt][1] = 0.f;
    }

#pragma unroll
    for (int mt = 0; mt < 4; mt++) {
        int rlo = p0 + wm * 64 + mt * 16 + (lane >> 2);
#pragma unroll
        for (int nt = 0; nt < 4; nt++) {
            int col = wn * 32 + nt * 8 + (lane & 3) * 2;
            float v0 = Vs[col], v1 = Vs[col + 1];
#pragma unroll
            for (int half = 0; half < 2; half++) {
                int row = rlo + half * 8;
                float e0 = __expf(acc[mt][nt][half * 2 + 0]);
                float e1 = __expf(acc[mt][nt][half * 2 + 1]);
                esum[mt][half] += e0 + e1;
                gsum[mt][half] += e0 * v0 + e1 * v1;
                float2 st = make_float2(e0, e1);
                *reinterpret_cast<float2*>(
                    g_expS + ((size_t)b * HWN + row) * HWN + q0 + col) = st;
            }
        }
    }

    // reduce each row-sum across the 4 lanes of the quad (same lane>>2)
#pragma unroll
    for (int mt = 0; mt < 4; mt++)
#pragma unroll
        for (int half = 0; half < 2; half++) {
#pragma unroll
            for (int off = 1; off <= 2; off <<= 1) {
                esum[mt][half] += __shfl_xor_sync(0xffffffffu, esum[mt][half], off);
                gsum[mt][half] += __shfl_xor_sync(0xffffffffu, gsum[mt][half], off);
            }
        }
    if ((lane & 3) == 0) {
#pragma unroll
        for (int mt = 0; mt < 4; mt++) {
            int rlo = p0 + wm * 64 + mt * 16 + (lane >> 2);
#pragma unroll
            for (int half = 0; half < 2; half++) {
                int row = rlo + half * 8;
                atomicAdd(&g_E[b * HWN + row], (double)esum[mt][half]);
                atomicAdd(&g_G[b * HWN + row], (double)gsum[mt][half]);
            }
        }
    }
}

// ---------------- output: masked correction + gather ------------------------
__global__ void out_kernel(const float* __restrict__ x, const int* __restrict__ lidx,
                           float* __restrict__ out) {
    int bf = blockIdx.x;
    int b = bf / NF, f = bf - b * NF;
    __shared__ int   sidx[FSZ];
    __shared__ float sgate[FSZ];
    int t = threadIdx.x;
    if (t < FSZ) sidx[t] = lidx[f * FSZ + t];
    __syncthreads();
    if (t < FSZ) {
        int p = sidx[t];
        const float* erow = g_expS + ((size_t)b * HWN + p) * HWN;
        double num = g_G[b * HWN + p];
        double den = g_E[b * HWN + p];
#pragma unroll
        for (int j = 0; j < FSZ; j++) {
            int q = sidx[j];
            double e = (double)erow[q];
            num -= e * (double)g_V[b * HWN + q];
            den -= e;
        }
        sgate[t] = (float)(num / (den + (double)EPSV));
    }
    __syncthreads();
    const float* xb = x + (size_t)b * HWN * CD;
    float o = 0.f;
#pragma unroll
    for (int p = 0; p < FSZ; p++)
        o += sgate[p] * xb[(size_t)sidx[p] * CD + t];
    out[(size_t)bf * CD + t] = o;
}

// ---------------- launch -----------------------------------------------------
extern "C" void kernel_launch(void* const* d_in, const int* in_sizes, int n_in,
                              void* d_out, int out_size) {
    const float* batch = (const float*)d_in[0];
    const float* Wq    = (const float*)d_in[1];
    const float* bq    = (const float*)d_in[2];
    const float* Wk    = (const float*)d_in[3];
    const float* bk    = (const float*)d_in[4];
    const float* wv    = (const float*)d_in[5];
    const float* bv    = (const float*)d_in[6];
    const int*   lidx  = (const int*)d_in[8];
    float* out = (float*)d_out;

    cudaFuncSetAttribute(gemm_proj_tc, cudaFuncAttributeMaxDynamicSharedMemorySize, SM_TOTAL);
    cudaFuncSetAttribute(gemm_s_tc,    cudaFuncAttributeMaxDynamicSharedMemorySize, SM_TOTAL);

    __nv_bfloat16 *xh, *xl, *wqh, *wql, *wkh, *wkl;
    cudaGetSymbolAddress((void**)&xh,  g_xh);
    cudaGetSymbolAddress((void**)&xl,  g_xl);
    cudaGetSymbolAddress((void**)&wqh, g_Wqh);
    cudaGetSymbolAddress((void**)&wql, g_Wql);
    cudaGetSymbolAddress((void**)&wkh, g_Wkh);
    cudaGetSymbolAddress((void**)&wkl, g_Wkl);

    zero_eg<<<(NB * HWN + 255) / 256, 256>>>();
    split_kernel<<<(NB * HWN * CD + 255) / 256, 256>>>(batch, xh, xl, NB * HWN * CD);
    split_kernel<<<(CD * CD + 255) / 256, 256>>>(Wq, wqh, wql, CD * CD);
    split_kernel<<<(CD * CD + 255) / 256, 256>>>(Wk, wkh, wkl, CD * CD);
    v_kernel<<<NB * HWN / 8, 256>>>(batch, wv, bv);
    gemm_proj_tc<<<dim3(64, 2), 256, SM_TOTAL>>>(bq, bk);
    gemm_s_tc<<<dim3(8, 8, NB), 256, SM_TOTAL>>>();
    out_kernel<<<NB * NF, 128>>>(batch, lidx, out);
}